// round 3
// baseline (speedup 1.0000x reference)
#include <cuda_runtime.h>
#include <cuda_bf16.h>

#define L 2048
#define CIN 16
#define GROUPS 4
#define CPG 4

// 256 MiB scratch for sparsemax output (lower triangle only is ever written;
// conv masks everything else). __device__ global = sanctioned scratch.
__device__ float g_probs[(size_t)CIN * L * L];

// ---------------------------------------------------------------------------
// Kernel 1: causal sparsemax per (channel, row) via Michelot fixed-point.
// One block (256 threads) per row. Row data lives in registers (8/thread).
// ---------------------------------------------------------------------------
__device__ __forceinline__ void block_reduce2(float& a, float& b,
                                              volatile float* sa, volatile float* sb,
                                              int tid) {
    int lane = tid & 31, wid = tid >> 5;
#pragma unroll
    for (int o = 16; o; o >>= 1) {
        a += __shfl_down_sync(0xffffffffu, a, o);
        b += __shfl_down_sync(0xffffffffu, b, o);
    }
    if (lane == 0) { sa[wid] = a; sb[wid] = b; }
    __syncthreads();
    if (tid == 0) {
        float A = 0.f, B = 0.f;
#pragma unroll
        for (int w = 0; w < 8; w++) { A += sa[w]; B += sb[w]; }
        sa[0] = A; sb[0] = B;
    }
    __syncthreads();
    a = sa[0]; b = sb[0];
    __syncthreads();  // protect scratch before next call
}

__global__ void __launch_bounds__(256) sparsemax_rows(const float* __restrict__ scores) {
    const int i = blockIdx.x;   // row 0..L-1
    const int c = blockIdx.y;   // channel 0..15
    const int n = i + 1;        // valid prefix length
    const int tid = threadIdx.x;

    const unsigned base = ((unsigned)c * L + (unsigned)i) * L;
    const float* src = scores + base;

    float z[8];
    float lsum = 0.f;
#pragma unroll
    for (int t = 0; t < 8; t++) {
        int j = tid + (t << 8);
        if (j < n) { z[t] = src[j]; lsum += z[t]; }
        else        { z[t] = -3.0e38f; }
    }

    __shared__ float sh_s[8], sh_c[8];

    float dummy = 0.f;
    float S = lsum;
    block_reduce2(S, dummy, sh_s, sh_c, tid);

    float tau = (S - 1.0f) / (float)n;
    float kprev = (float)n;

#pragma unroll 1
    for (int it = 0; it < 128; ++it) {
        float ls = 0.f, lc = 0.f;
#pragma unroll
        for (int t = 0; t < 8; t++) {
            if (z[t] > tau) { ls += z[t]; lc += 1.f; }
        }
        block_reduce2(ls, lc, sh_s, sh_c, tid);
        if (lc >= kprev || lc == 0.f) break;   // support stable (or degenerate) -> tau final
        tau = (ls - 1.0f) / lc;
        kprev = lc;
    }

    float* dst = g_probs + base;
#pragma unroll
    for (int t = 0; t < 8; t++) {
        int j = tid + (t << 8);
        if (j < n) dst[j] = fmaxf(z[t] - tau, 0.f);
    }
}

// ---------------------------------------------------------------------------
// Kernel 2: grouped 3x3 same-pad conv + bias + causal zeroing.
// grid = (4 col-tiles of 512, 2048 rows, 4 groups), 128 threads.
// Each thread: 4 columns x 4 output channels (weights amortized).
// Above-diagonal tiles: stream zeros only.
// ---------------------------------------------------------------------------
__global__ void __launch_bounds__(128) conv3x3_group(const float* __restrict__ weight,
                                                     const float* __restrict__ bias,
                                                     float* __restrict__ out) {
    const int g  = blockIdx.z;
    const int i  = blockIdx.y;
    const int j0 = blockIdx.x * 512;
    const int tid = threadIdx.x;

    if (j0 > i) {
        // entire tile above the diagonal -> zeros
        const float4 z4 = make_float4(0.f, 0.f, 0.f, 0.f);
#pragma unroll
        for (int co = 0; co < 4; co++) {
            unsigned o = ((unsigned)(g * 4 + co) * L + (unsigned)i) * L + (unsigned)(j0 + tid * 4);
            *reinterpret_cast<float4*>(out + o) = z4;
        }
        return;
    }

    __shared__ float s_in[4][3][516];   // 514 used, padded to 516 (16B aligned rows)
    __shared__ float s_w[144];
    __shared__ float s_b[4];

    // FIX (R2): blockDim is 128, so a strided loop is required to fill all
    // 144 weights (previously s_w[128..143] were uninitialized -> channels
    // 3/7/11/15 garbage -> rel_err 0.116).
#pragma unroll
    for (int e = tid; e < 144; e += 128) s_w[e] = weight[g * 144 + e];
    if (tid < 4) s_b[tid] = bias[g * 4 + tid];

    // load 4 in-ch x 3 rows x 516 cols (2 pad cols zeroed) with bounds +
    // causal masking
    const int total = 4 * 3 * 516;
    for (int e = tid; e < total; e += 128) {
        int u   = e / (3 * 516);
        int rem = e % (3 * 516);
        int r   = rem / 516;
        int col = rem % 516;
        int ii = i + r - 1;
        int jj = j0 - 1 + col;
        float v = 0.f;
        if (col < 514 && ii >= 0 && ii < L && jj >= 0 && jj <= ii)
            v = g_probs[((unsigned)(g * 4 + u) * L + (unsigned)ii) * L + (unsigned)jj];
        s_in[u][r][col] = v;
    }
    __syncthreads();

    const int jb = tid * 4;  // column offset within tile (smem col jb maps to jj = j0-1+jb)

    float acc[4][4];
#pragma unroll
    for (int co = 0; co < 4; co++)
#pragma unroll
        for (int q = 0; q < 4; q++) acc[co][q] = s_b[co];

#pragma unroll
    for (int u = 0; u < 4; u++) {
#pragma unroll
        for (int kh = 0; kh < 3; kh++) {
            // LDS.128 x2: conflict-free, covers the 6-wide input window
            const float4 a = *reinterpret_cast<const float4*>(&s_in[u][kh][jb]);
            const float4 b = *reinterpret_cast<const float4*>(&s_in[u][kh][jb + 4]);
            const float v0 = a.x, v1 = a.y, v2 = a.z, v3 = a.w, v4 = b.x, v5 = b.y;
#pragma unroll
            for (int co = 0; co < 4; co++) {
                const float w0 = s_w[co * 36 + u * 9 + kh * 3 + 0];
                const float w1 = s_w[co * 36 + u * 9 + kh * 3 + 1];
                const float w2 = s_w[co * 36 + u * 9 + kh * 3 + 2];
                acc[co][0] += v0 * w0 + v1 * w1 + v2 * w2;
                acc[co][1] += v1 * w0 + v2 * w1 + v3 * w2;
                acc[co][2] += v2 * w0 + v3 * w1 + v4 * w2;
                acc[co][3] += v3 * w0 + v4 * w1 + v5 * w2;
            }
        }
    }

    const int colb = j0 + jb;
#pragma unroll
    for (int co = 0; co < 4; co++) {
        float4 r4;
        r4.x = (colb + 0 <= i) ? acc[co][0] : 0.f;
        r4.y = (colb + 1 <= i) ? acc[co][1] : 0.f;
        r4.z = (colb + 2 <= i) ? acc[co][2] : 0.f;
        r4.w = (colb + 3 <= i) ? acc[co][3] : 0.f;
        unsigned o = ((unsigned)(g * 4 + co) * L + (unsigned)i) * L + (unsigned)colb;
        *reinterpret_cast<float4*>(out + o) = r4;
    }
}

extern "C" void kernel_launch(void* const* d_in, const int* in_sizes, int n_in,
                              void* d_out, int out_size) {
    const float* scores = (const float*)d_in[0];
    const float* weight = (const float*)d_in[1];
    const float* bias   = (const float*)d_in[2];
    float* out = (float*)d_out;

    sparsemax_rows<<<dim3(L, CIN), 256>>>(scores);
    conv3x3_group<<<dim3(L / 512, L, GROUPS), 128>>>(weight, bias, out);
}

// round 4
// speedup vs baseline: 1.4511x; 1.4511x over previous
#include <cuda_runtime.h>
#include <cuda_bf16.h>

#define L 2048
#define CIN 16
#define GROUPS 4
#define LS 2056              // padded scratch row stride in floats: 4 lead + 2048 + 4 trail
#define ROWS_P (L + 2)       // +1 guard row above and below per channel

// ~257 MiB padded scratch. Layout per channel c: rows 0..L+1 (row r holds data
// row r-1; rows 0 and L+1 are zero guards). Within a row: [0,4) lead pad (zero),
// [4,4+L) data, [4+L,2056) trail pad. Above-diagonal cols zero-filled to the end
// of the last 512-tile any conv consumer reads -> conv staging needs NO masking.
__device__ float g_probs[(size_t)CIN * ROWS_P * LS];

// ---------------------------------------------------------------------------
// Kernel 1: causal sparsemax per (channel, row), Michelot fixed point.
// 256 threads/block, row in registers (8/thread, float4 IO). 2 barriers/iter.
// ---------------------------------------------------------------------------
__global__ void __launch_bounds__(256) sparsemax_rows(const float* __restrict__ scores) {
    const int i = blockIdx.x;          // data row
    const int c = blockIdx.y;          // channel
    const int n = i + 1;               // valid prefix length
    const int tid = threadIdx.x;

    const float* src = scores + ((size_t)c * L + (size_t)i) * L;
    float* dst = g_probs + ((size_t)c * ROWS_P + (size_t)(i + 1)) * LS + 4;

    __shared__ float sa[16], sb[16];   // [0..7] warp partials, [8] final

    float z[8];
    float lsum = 0.f;
    const int c0 = tid * 4;
    const int c1 = 1024 + c0;
    if (c0 + 3 < n) {
        float4 v = *reinterpret_cast<const float4*>(src + c0);
        z[0] = v.x; z[1] = v.y; z[2] = v.z; z[3] = v.w;
        lsum += v.x + v.y + v.z + v.w;
    } else {
#pragma unroll
        for (int q = 0; q < 4; q++) {
            int j = c0 + q;
            if (j < n) { z[q] = src[j]; lsum += z[q]; } else z[q] = -3.0e38f;
        }
    }
    if (c1 + 3 < n) {
        float4 v = *reinterpret_cast<const float4*>(src + c1);
        z[4] = v.x; z[5] = v.y; z[6] = v.z; z[7] = v.w;
        lsum += v.x + v.y + v.z + v.w;
    } else {
#pragma unroll
        for (int q = 0; q < 4; q++) {
            int j = c1 + q;
            if (j < n) { z[4 + q] = src[j]; lsum += z[4 + q]; } else z[4 + q] = -3.0e38f;
        }
    }

    // two-barrier block reduction of (a,b)
    auto reduce2 = [&](float& a, float& b) {
#pragma unroll
        for (int o = 16; o; o >>= 1) {
            a += __shfl_down_sync(0xffffffffu, a, o);
            b += __shfl_down_sync(0xffffffffu, b, o);
        }
        if ((tid & 31) == 0) { sa[tid >> 5] = a; sb[tid >> 5] = b; }
        __syncthreads();
        if (tid < 32) {
            float A = (tid < 8) ? sa[tid] : 0.f;
            float B = (tid < 8) ? sb[tid] : 0.f;
#pragma unroll
            for (int o = 4; o; o >>= 1) {
                A += __shfl_down_sync(0xffffffffu, A, o);
                B += __shfl_down_sync(0xffffffffu, B, o);
            }
            if (tid == 0) { sa[8] = A; sb[8] = B; }
        }
        __syncthreads();
        a = sa[8]; b = sb[8];
    };

    float S = lsum, dummy = 0.f;
    reduce2(S, dummy);

    float tau = (S - 1.0f) / (float)n;
    float kprev = (float)n;

#pragma unroll 1
    for (int it = 0; it < 64; ++it) {
        float ls = 0.f, lc = 0.f;
#pragma unroll
        for (int q = 0; q < 8; q++)
            if (z[q] > tau) { ls += z[q]; lc += 1.f; }
        reduce2(ls, lc);
        if (lc >= kprev || lc == 0.f) break;   // support stable -> tau final
        tau = (ls - 1.0f) / lc;
        kprev = lc;
    }

    // store probs (float4 fast path)
    if (c0 + 3 < n) {
        float4 r;
        r.x = fmaxf(z[0] - tau, 0.f); r.y = fmaxf(z[1] - tau, 0.f);
        r.z = fmaxf(z[2] - tau, 0.f); r.w = fmaxf(z[3] - tau, 0.f);
        *reinterpret_cast<float4*>(dst + c0) = r;
    } else {
#pragma unroll
        for (int q = 0; q < 4; q++) { int j = c0 + q; if (j < n) dst[j] = fmaxf(z[q] - tau, 0.f); }
    }
    if (c1 + 3 < n) {
        float4 r;
        r.x = fmaxf(z[4] - tau, 0.f); r.y = fmaxf(z[5] - tau, 0.f);
        r.z = fmaxf(z[6] - tau, 0.f); r.w = fmaxf(z[7] - tau, 0.f);
        *reinterpret_cast<float4*>(dst + c1) = r;
    } else {
#pragma unroll
        for (int q = 0; q < 4; q++) { int j = c1 + q; if (j < n) dst[j] = fmaxf(z[4 + q] - tau, 0.f); }
    }

    // lead pad
    if (tid < 4) dst[tid - 4] = 0.f;
    // zero-fill above diagonal through end of last 512-tile a consumer reads (+4 pad)
    const int E = min(2052, (n >> 9) * 512 + 516);
    for (int j = n + tid; j < E; j += 256) dst[j] = 0.f;
    // zero guard rows (full padded width)
    if (i == 0) {
        float4* gr = reinterpret_cast<float4*>(g_probs + (size_t)c * ROWS_P * LS);
        const float4 z4 = make_float4(0.f, 0.f, 0.f, 0.f);
        for (int j = tid; j < LS / 4; j += 256) gr[j] = z4;
    }
    if (i == L - 1) {
        float4* gr = reinterpret_cast<float4*>(g_probs + ((size_t)c * ROWS_P + (size_t)(L + 1)) * LS);
        const float4 z4 = make_float4(0.f, 0.f, 0.f, 0.f);
        for (int j = tid; j < LS / 4; j += 256) gr[j] = z4;
    }
}

// ---------------------------------------------------------------------------
// Kernel 2: grouped 3x3 conv + bias + causal zero. Branch-free vector staging
// from the padded scratch (all masking pre-done by K1).
// grid = (4 tiles of 512, 2048 rows, 4 groups), 128 threads.
// smem plane p=(u*3+r) col s holds jj = j0-4+s, s in [0,520).
// ---------------------------------------------------------------------------
__global__ void __launch_bounds__(128) conv3x3_group(const float* __restrict__ weight,
                                                     const float* __restrict__ bias,
                                                     float* __restrict__ out) {
    const int g  = blockIdx.z;
    const int i  = blockIdx.y;
    const int j0 = blockIdx.x * 512;
    const int tid = threadIdx.x;

    if (j0 > i) {  // whole tile above diagonal -> zeros
        const float4 z4 = make_float4(0.f, 0.f, 0.f, 0.f);
#pragma unroll
        for (int co = 0; co < 4; co++) {
            size_t o = ((size_t)(g * 4 + co) * L + (size_t)i) * L + (size_t)(j0 + tid * 4);
            *reinterpret_cast<float4*>(out + o) = z4;
        }
        return;
    }

    __shared__ float s_in[12][528];   // 520 used per plane, stride-pad to 528
    __shared__ float s_w[144];
    __shared__ float s_b[4];

    for (int e = tid; e < 144; e += 128) s_w[e] = weight[g * 144 + e];
    if (tid < 4) s_b[tid] = bias[g * 4 + tid];

    // branch-free staging: 12 planes x 130 float4 (LDG.128 -> STS.128)
#pragma unroll
    for (int u = 0; u < 4; u++) {
#pragma unroll
        for (int r = 0; r < 3; r++) {
            const float4* src = reinterpret_cast<const float4*>(
                g_probs + ((size_t)(g * 4 + u) * ROWS_P + (size_t)(i + r)) * LS + (size_t)j0);
            float4* dp = reinterpret_cast<float4*>(&s_in[u * 3 + r][0]);
            dp[tid] = src[tid];
            if (tid < 2) dp[128 + tid] = src[128 + tid];
        }
    }
    __syncthreads();

    float acc[4][4];
#pragma unroll
    for (int co = 0; co < 4; co++)
#pragma unroll
        for (int q = 0; q < 4; q++) acc[co][q] = s_b[co];

#pragma unroll
    for (int u = 0; u < 4; u++) {
#pragma unroll
        for (int kh = 0; kh < 3; kh++) {
            const float4* rowp = reinterpret_cast<const float4*>(&s_in[u * 3 + kh][0]);
            const float4 a = rowp[tid];
            const float4 b = rowp[tid + 1];
            const float4 cq = rowp[tid + 2];
            // v[m] = input at jj = colb - 1 + m, colb = j0 + 4*tid
            const float v0 = a.w, v1 = b.x, v2 = b.y, v3 = b.z, v4 = b.w, v5 = cq.x;
#pragma unroll
            for (int co = 0; co < 4; co++) {
                const float w0 = s_w[co * 36 + u * 9 + kh * 3 + 0];
                const float w1 = s_w[co * 36 + u * 9 + kh * 3 + 1];
                const float w2 = s_w[co * 36 + u * 9 + kh * 3 + 2];
                acc[co][0] += v0 * w0 + v1 * w1 + v2 * w2;
                acc[co][1] += v1 * w0 + v2 * w1 + v3 * w2;
                acc[co][2] += v2 * w0 + v3 * w1 + v4 * w2;
                acc[co][3] += v3 * w0 + v4 * w1 + v5 * w2;
            }
        }
    }

    const int colb = j0 + tid * 4;
#pragma unroll
    for (int co = 0; co < 4; co++) {
        float4 r4;
        r4.x = (colb + 0 <= i) ? acc[co][0] : 0.f;
        r4.y = (colb + 1 <= i) ? acc[co][1] : 0.f;
        r4.z = (colb + 2 <= i) ? acc[co][2] : 0.f;
        r4.w = (colb + 3 <= i) ? acc[co][3] : 0.f;
        size_t o = ((size_t)(g * 4 + co) * L + (size_t)i) * L + (size_t)colb;
        *reinterpret_cast<float4*>(out + o) = r4;
    }
}

extern "C" void kernel_launch(void* const* d_in, const int* in_sizes, int n_in,
                              void* d_out, int out_size) {
    const float* scores = (const float*)d_in[0];
    const float* weight = (const float*)d_in[1];
    const float* bias   = (const float*)d_in[2];
    float* out = (float*)d_out;

    sparsemax_rows<<<dim3(L, CIN), 256>>>(scores);
    conv3x3_group<<<dim3(L / 512, L, GROUPS), 128>>>(weight, bias, out);
}

// round 6
// speedup vs baseline: 1.9450x; 1.3403x over previous
#include <cuda_runtime.h>
#include <cuda_bf16.h>

#define L 2048
#define CIN 16
#define GROUPS 4
#define LS 2056              // padded scratch row stride: 4 lead + 2048 + 4 trail
#define ROWS_P (L + 2)       // +1 zero guard row above and below per channel

// ~257 MiB padded scratch. Channel c, padded row r holds data row r-1 (rows 0
// and L+1 are zero guards). Cols: [0,4) lead pad, [4,4+L) data, trail pad.
// Above-diagonal cols zero-filled through the last 512-tile any conv consumer
// reads, so conv staging is fully branch-free.
__device__ float g_probs[(size_t)CIN * ROWS_P * LS];

// ---------------------------------------------------------------------------
// Kernel 1: causal sparsemax, ONE WARP PER ROW. Row in registers (64/lane),
// Michelot fixed point with shfl.bfly reductions. No barriers, no smem.
// block = 256 (8 warps = 8 rows), grid = (L/8, CIN).
// ---------------------------------------------------------------------------
__global__ void __launch_bounds__(256) sparsemax_rows(const float* __restrict__ scores) {
    const int tid  = threadIdx.x;
    const int w    = tid >> 5;
    const int lane = tid & 31;
    const int i    = (blockIdx.x << 3) + w;   // data row
    const int c    = blockIdx.y;              // channel
    const int n    = i + 1;                   // valid prefix length

    const float* src = scores + ((size_t)c * L + (size_t)i) * L;
    float* dst = g_probs + ((size_t)c * ROWS_P + (size_t)(i + 1)) * LS + 4;

    const int full = n >> 7;        // chunks [0,full) are fully valid (128 cols each)
    const int base = lane << 2;     // lane*4 within a chunk

    float z[64];
    float S = 0.f;
#pragma unroll
    for (int t = 0; t < 16; t++) {
        if (t < full) {
            float4 v = *reinterpret_cast<const float4*>(src + (t << 7) + base);
            z[4 * t + 0] = v.x; z[4 * t + 1] = v.y;
            z[4 * t + 2] = v.z; z[4 * t + 3] = v.w;
            S += (v.x + v.y) + (v.z + v.w);
        } else if (t == full) {
#pragma unroll
            for (int q = 0; q < 4; q++) {
                int j = (t << 7) + base + q;
                float v = -3.0e38f;
                if (j < n) { v = src[j]; S += v; }
                z[4 * t + q] = v;
            }
        }
        // t > full: never read (all later loops break at t > full)
    }

#pragma unroll
    for (int o = 16; o; o >>= 1) S += __shfl_xor_sync(0xffffffffu, S, o);

    float tau = (S - 1.0f) / (float)n;
    float kprev = (float)n;

#pragma unroll 1
    for (int it = 0; it < 64; ++it) {
        float ls = 0.f, lc = 0.f;
#pragma unroll
        for (int t = 0; t < 16; t++) {
            if (t > full) break;          // warp-uniform
#pragma unroll
            for (int q = 0; q < 4; q++) {
                float zz = z[4 * t + q];
                if (zz > tau) { ls += zz; lc += 1.f; }
            }
        }
#pragma unroll
        for (int o = 16; o; o >>= 1) {
            ls += __shfl_xor_sync(0xffffffffu, ls, o);
            lc += __shfl_xor_sync(0xffffffffu, lc, o);
        }
        if (lc >= kprev || lc == 0.f) break;   // support stable -> tau final
        tau = (ls - 1.0f) / lc;
        kprev = lc;
    }

    // store probs
#pragma unroll
    for (int t = 0; t < 16; t++) {
        if (t > full) break;
        if (t < full) {
            float4 r;
            r.x = fmaxf(z[4 * t + 0] - tau, 0.f);
            r.y = fmaxf(z[4 * t + 1] - tau, 0.f);
            r.z = fmaxf(z[4 * t + 2] - tau, 0.f);
            r.w = fmaxf(z[4 * t + 3] - tau, 0.f);
            *reinterpret_cast<float4*>(dst + (t << 7) + base) = r;
        } else {
#pragma unroll
            for (int q = 0; q < 4; q++) {
                int j = (t << 7) + base + q;
                if (j < n) dst[j] = fmaxf(z[4 * t + q] - tau, 0.f);
            }
        }
    }

    // lead pad
    if (lane < 4) dst[lane - 4] = 0.f;
    // zero-fill above diagonal through the last tile any consumer (j0 <= n+1) reads
    const int E = min(2052, ((((n + 1) >> 9) << 9) + 516));
    for (int j = n + lane; j < E; j += 32) dst[j] = 0.f;
    // zero guard rows
    if (i == 0) {
        float4* gr = reinterpret_cast<float4*>(g_probs + (size_t)c * ROWS_P * LS);
        const float4 z4 = make_float4(0.f, 0.f, 0.f, 0.f);
        for (int j = lane; j < LS / 4; j += 32) gr[j] = z4;
    }
    if (i == L - 1) {
        float4* gr = reinterpret_cast<float4*>(
            g_probs + ((size_t)c * ROWS_P + (size_t)(L + 1)) * LS);
        const float4 z4 = make_float4(0.f, 0.f, 0.f, 0.f);
        for (int j = lane; j < LS / 4; j += 32) gr[j] = z4;
    }
}

// ---------------------------------------------------------------------------
// Kernel 2: grouped 3x3 conv + bias + causal zero, TWO output rows per block.
// Stages 4 input rows (16 planes), shares middle rows' windows in registers.
// grid = (4 tiles of 512, L/2 row-pairs, 4 groups), 128 threads.
// ---------------------------------------------------------------------------
__global__ void __launch_bounds__(128) conv3x3_group(const float* __restrict__ weight,
                                                     const float* __restrict__ bias,
                                                     float* __restrict__ out) {
    const int g   = blockIdx.z;
    const int i0  = blockIdx.y * 2;
    const int j0  = blockIdx.x * 512;
    const int tid = threadIdx.x;

    if (j0 > i0 + 1) {  // both rows entirely above diagonal -> zeros
        const float4 z4 = make_float4(0.f, 0.f, 0.f, 0.f);
#pragma unroll
        for (int ro = 0; ro < 2; ro++)
#pragma unroll
            for (int co = 0; co < 4; co++) {
                size_t o = ((size_t)(g * 4 + co) * L + (size_t)(i0 + ro)) * L
                         + (size_t)(j0 + tid * 4);
                *reinterpret_cast<float4*>(out + o) = z4;
            }
        return;
    }

    __shared__ float s_in[16][528];   // 4 in-ch x 4 rows, 520 used, stride-pad 528
    __shared__ float s_w[144];
    __shared__ float s_b[4];

    for (int e = tid; e < 144; e += 128) s_w[e] = weight[g * 144 + e];
    if (tid < 4) s_b[tid] = bias[g * 4 + tid];

    // branch-free staging: 16 planes x 130 float4 (padded row i0+r = data row i0-1+r)
#pragma unroll
    for (int u = 0; u < 4; u++) {
#pragma unroll
        for (int r = 0; r < 4; r++) {
            const float4* src = reinterpret_cast<const float4*>(
                g_probs + ((size_t)(g * 4 + u) * ROWS_P + (size_t)(i0 + r)) * LS + (size_t)j0);
            float4* dp = reinterpret_cast<float4*>(&s_in[u * 4 + r][0]);
            dp[tid] = src[tid];
            if (tid < 2) dp[128 + tid] = src[128 + tid];
        }
    }
    __syncthreads();

    float acc[2][4][4];
#pragma unroll
    for (int ro = 0; ro < 2; ro++)
#pragma unroll
        for (int co = 0; co < 4; co++)
#pragma unroll
            for (int q = 0; q < 4; q++) acc[ro][co][q] = s_b[co];

#pragma unroll
    for (int u = 0; u < 4; u++) {
        float win[4][6];
#pragma unroll
        for (int r = 0; r < 4; r++) {
            const float4* rowp = reinterpret_cast<const float4*>(&s_in[u * 4 + r][0]);
            const float4 a = rowp[tid];
            const float4 b = rowp[tid + 1];
            const float4 cc = rowp[tid + 2];
            win[r][0] = a.w; win[r][1] = b.x; win[r][2] = b.y;
            win[r][3] = b.z; win[r][4] = b.w; win[r][5] = cc.x;
        }
#pragma unroll
        for (int ro = 0; ro < 2; ro++) {
#pragma unroll
            for (int kh = 0; kh < 3; kh++) {
                const float* v = win[ro + kh];
#pragma unroll
                for (int co = 0; co < 4; co++) {
                    const float w0 = s_w[co * 36 + u * 9 + kh * 3 + 0];
                    const float w1 = s_w[co * 36 + u * 9 + kh * 3 + 1];
                    const float w2 = s_w[co * 36 + u * 9 + kh * 3 + 2];
                    acc[ro][co][0] += v[0] * w0 + v[1] * w1 + v[2] * w2;
                    acc[ro][co][1] += v[1] * w0 + v[2] * w1 + v[3] * w2;
                    acc[ro][co][2] += v[2] * w0 + v[3] * w1 + v[4] * w2;
                    acc[ro][co][3] += v[3] * w0 + v[4] * w1 + v[5] * w2;
                }
            }
        }
    }

    const int colb = j0 + tid * 4;
#pragma unroll
    for (int ro = 0; ro < 2; ro++) {
        const int ii = i0 + ro;
#pragma unroll
        for (int co = 0; co < 4; co++) {
            float4 r4;
            r4.x = (colb + 0 <= ii) ? acc[ro][co][0] : 0.f;
            r4.y = (colb + 1 <= ii) ? acc[ro][co][1] : 0.f;
            r4.z = (colb + 2 <= ii) ? acc[ro][co][2] : 0.f;
            r4.w = (colb + 3 <= ii) ? acc[ro][co][3] : 0.f;
            size_t o = ((size_t)(g * 4 + co) * L + (size_t)ii) * L + (size_t)colb;
            *reinterpret_cast<float4*>(out + o) = r4;
        }
    }
}

extern "C" void kernel_launch(void* const* d_in, const int* in_sizes, int n_in,
                              void* d_out, int out_size) {
    const float* scores = (const float*)d_in[0];
    const float* weight = (const float*)d_in[1];
    const float* bias   = (const float*)d_in[2];
    float* out = (float*)d_out;

    sparsemax_rows<<<dim3(L / 8, CIN), 256>>>(scores);
    conv3x3_group<<<dim3(L / 512, L / 2, GROUPS), 128>>>(weight, bias, out);
}

// round 7
// speedup vs baseline: 2.2823x; 1.1734x over previous
#include <cuda_runtime.h>
#include <cuda_fp16.h>

#define L 2048
#define CIN 16
#define GROUPS 4
#define LS 2056              // padded scratch row stride in HALVES: 4 lead + 2048 + 4 trail
#define ROWS_P (L + 2)       // +1 zero guard row above and below per channel

// ~135 MiB fp16 scratch. Channel c, padded row r holds data row r-1 (rows 0
// and L+1 zero guards). Cols: [0,4) lead pad, [4,4+L) data, trail pad.
// Above-diagonal cols zero-filled through the last 512-tile any conv consumer
// reads, so conv staging is fully branch-free.
__device__ __half g_probs[(size_t)CIN * ROWS_P * LS];

// ---------------------------------------------------------------------------
// Kernel 1: causal sparsemax, ONE WARP PER ROW. Michelot fixed point with a
// tight start tau0 = max((S-1)/n, max(z)-1)  [valid: tau* >= zmax-1 always].
// Row in registers, shfl reductions, no barriers/smem. fp16 output.
// ---------------------------------------------------------------------------
__global__ void __launch_bounds__(256) sparsemax_rows(const float* __restrict__ scores) {
    const int tid  = threadIdx.x;
    const int w    = tid >> 5;
    const int lane = tid & 31;
    const int i    = (blockIdx.x << 3) + w;   // data row
    const int c    = blockIdx.y;              // channel
    const int n    = i + 1;                   // valid prefix length

    const float* src = scores + ((size_t)c * L + (size_t)i) * L;
    __half* dst = g_probs + ((size_t)c * ROWS_P + (size_t)(i + 1)) * LS + 4;

    const int full = n >> 7;        // chunks [0,full) fully valid (128 cols each)
    const int base = lane << 2;

    float z[64];
    float S = 0.f;
    float M = -3.0e38f;
#pragma unroll
    for (int t = 0; t < 16; t++) {
        if (t < full) {
            float4 v = *reinterpret_cast<const float4*>(src + (t << 7) + base);
            z[4 * t + 0] = v.x; z[4 * t + 1] = v.y;
            z[4 * t + 2] = v.z; z[4 * t + 3] = v.w;
            S += (v.x + v.y) + (v.z + v.w);
            M = fmaxf(M, fmaxf(fmaxf(v.x, v.y), fmaxf(v.z, v.w)));
        } else if (t == full) {
#pragma unroll
            for (int q = 0; q < 4; q++) {
                int j = (t << 7) + base + q;
                float v = -3.0e38f;
                if (j < n) { v = src[j]; S += v; M = fmaxf(M, v); }
                z[4 * t + q] = v;
            }
        }
    }

#pragma unroll
    for (int o = 16; o; o >>= 1) {
        S += __shfl_xor_sync(0xffffffffu, S, o);
        M = fmaxf(M, __shfl_xor_sync(0xffffffffu, M, o));
    }

    // tight start: tau* >= zmax - 1 (since sum of (z-tau*)+ = 1 bounds zmax-tau*)
    float tau = fmaxf((S - 1.0f) / (float)n, M - 1.0f);
    float kprev = 3.0e38f;   // must NOT allow a break before the first tau update

#pragma unroll 1
    for (int it = 0; it < 64; ++it) {
        float ls = 0.f, lc = 0.f;
#pragma unroll
        for (int t = 0; t < 16; t++) {
            if (t > full) break;          // warp-uniform
#pragma unroll
            for (int q = 0; q < 4; q++) {
                float zz = z[4 * t + q];
                if (zz > tau) { ls += zz; lc += 1.f; }
            }
        }
#pragma unroll
        for (int o = 16; o; o >>= 1) {
            ls += __shfl_xor_sync(0xffffffffu, ls, o);
            lc += __shfl_xor_sync(0xffffffffu, lc, o);
        }
        if (lc >= kprev || lc == 0.f) break;   // support stable -> tau is fixed point
        tau = (ls - 1.0f) / lc;
        kprev = lc;
    }

    // store probs as fp16 (uint2 = 4 halves per chunk-lane)
#pragma unroll
    for (int t = 0; t < 16; t++) {
        if (t > full) break;
        if (t < full) {
            __half2 h0 = __floats2half2_rn(fmaxf(z[4 * t + 0] - tau, 0.f),
                                           fmaxf(z[4 * t + 1] - tau, 0.f));
            __half2 h1 = __floats2half2_rn(fmaxf(z[4 * t + 2] - tau, 0.f),
                                           fmaxf(z[4 * t + 3] - tau, 0.f));
            uint2 pk;
            pk.x = *reinterpret_cast<unsigned*>(&h0);
            pk.y = *reinterpret_cast<unsigned*>(&h1);
            *reinterpret_cast<uint2*>(dst + (t << 7) + base) = pk;
        } else {
#pragma unroll
            for (int q = 0; q < 4; q++) {
                int j = (t << 7) + base + q;
                if (j < n) dst[j] = __float2half_rn(fmaxf(z[4 * t + q] - tau, 0.f));
            }
        }
    }

    const __half hz = __ushort_as_half((unsigned short)0);
    // lead pad
    if (lane < 4) dst[lane - 4] = hz;
    // zero-fill above diagonal through the last tile any consumer reads
    const int E = min(2052, ((((n + 1) >> 9) << 9) + 516));
    for (int j = n + lane; j < E; j += 32) dst[j] = hz;
    // zero guard rows (full padded width: 2056 halves = 257 uint4)
    if (i == 0) {
        uint4* gr = reinterpret_cast<uint4*>(g_probs + (size_t)c * ROWS_P * LS);
        const uint4 z4 = make_uint4(0u, 0u, 0u, 0u);
        for (int j = lane; j < LS / 8; j += 32) gr[j] = z4;
    }
    if (i == L - 1) {
        uint4* gr = reinterpret_cast<uint4*>(
            g_probs + ((size_t)c * ROWS_P + (size_t)(L + 1)) * LS);
        const uint4 z4 = make_uint4(0u, 0u, 0u, 0u);
        for (int j = lane; j < LS / 8; j += 32) gr[j] = z4;
    }
}

// ---------------------------------------------------------------------------
// Kernel 2: grouped 3x3 conv + bias + causal zero, TWO output rows per block.
// Stages 4 input rows (16 planes) fp16->fp32 into smem (convert once per
// element); inner FMA loop identical to the fp32 version.
// grid = (4 tiles of 512, L/2 row-pairs, 4 groups), 128 threads.
// ---------------------------------------------------------------------------
__global__ void __launch_bounds__(128) conv3x3_group(const float* __restrict__ weight,
                                                     const float* __restrict__ bias,
                                                     float* __restrict__ out) {
    const int g   = blockIdx.z;
    const int i0  = blockIdx.y * 2;
    const int j0  = blockIdx.x * 512;
    const int tid = threadIdx.x;

    if (j0 > i0 + 1) {  // both rows entirely above diagonal -> zeros
        const float4 z4 = make_float4(0.f, 0.f, 0.f, 0.f);
#pragma unroll
        for (int ro = 0; ro < 2; ro++)
#pragma unroll
            for (int co = 0; co < 4; co++) {
                size_t o = ((size_t)(g * 4 + co) * L + (size_t)(i0 + ro)) * L
                         + (size_t)(j0 + tid * 4);
                *reinterpret_cast<float4*>(out + o) = z4;
            }
        return;
    }

    __shared__ float s_in[16][528];   // fp32 planes: 520 used, stride-pad 528
    __shared__ float s_w[144];
    __shared__ float s_b[4];

    for (int e = tid; e < 144; e += 128) s_w[e] = weight[g * 144 + e];
    if (tid < 4) s_b[tid] = bias[g * 4 + tid];

    // staging: LDG.64 of 4 halves -> convert -> STS.128 float4. 130 per plane.
#pragma unroll
    for (int u = 0; u < 4; u++) {
#pragma unroll
        for (int r = 0; r < 4; r++) {
            const uint2* src = reinterpret_cast<const uint2*>(
                g_probs + ((size_t)(g * 4 + u) * ROWS_P + (size_t)(i0 + r)) * LS + (size_t)j0);
            float4* dp = reinterpret_cast<float4*>(&s_in[u * 4 + r][0]);
            {
                uint2 v = src[tid];
                float2 f0 = __half22float2(*reinterpret_cast<__half2*>(&v.x));
                float2 f1 = __half22float2(*reinterpret_cast<__half2*>(&v.y));
                dp[tid] = make_float4(f0.x, f0.y, f1.x, f1.y);
            }
            if (tid < 2) {
                uint2 v = src[128 + tid];
                float2 f0 = __half22float2(*reinterpret_cast<__half2*>(&v.x));
                float2 f1 = __half22float2(*reinterpret_cast<__half2*>(&v.y));
                dp[128 + tid] = make_float4(f0.x, f0.y, f1.x, f1.y);
            }
        }
    }
    __syncthreads();

    float acc[2][4][4];
#pragma unroll
    for (int ro = 0; ro < 2; ro++)
#pragma unroll
        for (int co = 0; co < 4; co++)
#pragma unroll
            for (int q = 0; q < 4; q++) acc[ro][co][q] = s_b[co];

#pragma unroll
    for (int u = 0; u < 4; u++) {
        float win[4][6];
#pragma unroll
        for (int r = 0; r < 4; r++) {
            const float4* rowp = reinterpret_cast<const float4*>(&s_in[u * 4 + r][0]);
            const float4 a = rowp[tid];
            const float4 b = rowp[tid + 1];
            const float4 cc = rowp[tid + 2];
            win[r][0] = a.w; win[r][1] = b.x; win[r][2] = b.y;
            win[r][3] = b.z; win[r][4] = b.w; win[r][5] = cc.x;
        }
#pragma unroll
        for (int ro = 0; ro < 2; ro++) {
#pragma unroll
            for (int kh = 0; kh < 3; kh++) {
                const float* v = win[ro + kh];
#pragma unroll
                for (int co = 0; co < 4; co++) {
                    const float w0 = s_w[co * 36 + u * 9 + kh * 3 + 0];
                    const float w1 = s_w[co * 36 + u * 9 + kh * 3 + 1];
                    const float w2 = s_w[co * 36 + u * 9 + kh * 3 + 2];
                    acc[ro][co][0] += v[0] * w0 + v[1] * w1 + v[2] * w2;
                    acc[ro][co][1] += v[1] * w0 + v[2] * w1 + v[3] * w2;
                    acc[ro][co][2] += v[2] * w0 + v[3] * w1 + v[4] * w2;
                    acc[ro][co][3] += v[3] * w0 + v[4] * w1 + v[5] * w2;
                }
            }
        }
    }

    const int colb = j0 + tid * 4;
#pragma unroll
    for (int ro = 0; ro < 2; ro++) {
        const int ii = i0 + ro;
#pragma unroll
        for (int co = 0; co < 4; co++) {
            float4 r4;
            r4.x = (colb + 0 <= ii) ? acc[ro][co][0] : 0.f;
            r4.y = (colb + 1 <= ii) ? acc[ro][co][1] : 0.f;
            r4.z = (colb + 2 <= ii) ? acc[ro][co][2] : 0.f;
            r4.w = (colb + 3 <= ii) ? acc[ro][co][3] : 0.f;
            size_t o = ((size_t)(g * 4 + co) * L + (size_t)ii) * L + (size_t)colb;
            *reinterpret_cast<float4*>(out + o) = r4;
        }
    }
}

extern "C" void kernel_launch(void* const* d_in, const int* in_sizes, int n_in,
                              void* d_out, int out_size) {
    const float* scores = (const float*)d_in[0];
    const float* weight = (const float*)d_in[1];
    const float* bias   = (const float*)d_in[2];
    float* out = (float*)d_out;

    sparsemax_rows<<<dim3(L / 8, CIN), 256>>>(scores);
    conv3x3_group<<<dim3(L / 512, L / 2, GROUPS), 128>>>(weight, bias, out);
}

// round 9
// speedup vs baseline: 3.0238x; 1.3249x over previous
#include <cuda_runtime.h>
#include <cuda_fp16.h>

#define L 2048
#define CIN 16
#define GROUPS 4
#define LS 2056              // padded scratch row stride in HALVES: 4 lead + 2048 + 4 trail
#define ROWS_P (L + 2)       // +1 zero guard row above and below per channel

// ~135 MiB fp16 scratch. Channel c, padded row r holds data row r-1 (rows 0
// and L+1 zero guards). Cols: [0,4) lead pad, [4,4+L) data, trail pad.
// Above-diagonal cols zero-filled through the last 512-tile any conv consumer
// reads, so conv staging is fully branch-free.
__device__ __half g_probs[(size_t)CIN * ROWS_P * LS];

// ---------------------------------------------------------------------------
// Kernel 1: causal sparsemax, ONE WARP PER ROW.
// Loads: 16 predicated LDG.128 issued back-to-back (branch-free) -> MLP ~16.
// Michelot fixed point from tight tau0 = max((S-1)/n, max-1); shfl reductions.
// Store pass emits probs AND the above-diagonal zero-fill as vector stores.
// ---------------------------------------------------------------------------
__global__ void __launch_bounds__(256) sparsemax_rows(const float* __restrict__ scores) {
    const int tid  = threadIdx.x;
    const int w    = tid >> 5;
    const int lane = tid & 31;
    const int i    = (blockIdx.x << 3) + w;   // data row
    const int c    = blockIdx.y;              // channel
    const int n    = i + 1;                   // valid prefix length

    const float* src = scores + ((size_t)c * L + (size_t)i) * L;
    __half* dst = g_probs + ((size_t)c * ROWS_P + (size_t)(i + 1)) * LS + 4;

    const int full = n >> 7;        // chunks [0,full) fully valid (128 cols each)
    const int base = lane << 2;

    float z[64];
    // ---- branch-free predicated load pass: 16 consecutive @P LDG.128 ----
#pragma unroll
    for (int t = 0; t < 16; t++) {
        if (t <= full) {   // small predicable body -> @P LDG.128, no branch
            *reinterpret_cast<float4*>(&z[4 * t]) =
                *reinterpret_cast<const float4*>(src + (t << 7) + base);
        }
    }
    // mask the partial chunk (static register indices; warp-uniform branch)
#pragma unroll
    for (int t = 0; t < 16; t++) {
        if (t == full) {
#pragma unroll
            for (int q = 0; q < 4; q++)
                if ((t << 7) + base + q >= n) z[4 * t + q] = -3.0e38f;
        }
    }

    // ---- register-only sum + max pass ----
    float S = 0.f, M = -3.0e38f;
#pragma unroll
    for (int t = 0; t < 16; t++) {
        if (t > full) break;            // warp-uniform
#pragma unroll
        for (int q = 0; q < 4; q++) {
            float zz = z[4 * t + q];
            if (zz > -3.0e38f) S += zz; // masked lanes contribute nothing
            M = fmaxf(M, zz);
        }
    }
#pragma unroll
    for (int o = 16; o; o >>= 1) {
        S += __shfl_xor_sync(0xffffffffu, S, o);
        M = fmaxf(M, __shfl_xor_sync(0xffffffffu, M, o));
    }

    // tight start: tau* >= zmax - 1 (sum of (z-tau*)+ = 1 bounds zmax - tau*)
    float tau = fmaxf((S - 1.0f) / (float)n, M - 1.0f);
    float kprev = 3.0e38f;   // no break before first tau update

#pragma unroll 1
    for (int it = 0; it < 64; ++it) {
        float ls = 0.f, lc = 0.f;
#pragma unroll
        for (int t = 0; t < 16; t++) {
            if (t > full) break;        // warp-uniform
#pragma unroll
            for (int q = 0; q < 4; q++) {
                float zz = z[4 * t + q];
                if (zz > tau) { ls += zz; lc += 1.f; }
            }
        }
#pragma unroll
        for (int o = 16; o; o >>= 1) {
            ls += __shfl_xor_sync(0xffffffffu, ls, o);
            lc += __shfl_xor_sync(0xffffffffu, lc, o);
        }
        if (lc >= kprev || lc == 0.f) break;   // support stable -> fixed point
        tau = (ls - 1.0f) / lc;
        kprev = lc;
    }

    // ---- combined store + zero-fill pass (uint2 = 4 halves per lane-chunk) ----
    // fill extent: last 512-tile any consumer (j0 <= i+2) reads, + window tail
    const int E  = min(2052, ((((n + 1) >> 9) << 9) + 516));
    const int EC = (E + 127) >> 7;      // chunks (of 128) to touch, <= 17
#pragma unroll
    for (int t = 0; t < 16; t++) {
        if (t < full) {
            __half2 h0 = __floats2half2_rn(fmaxf(z[4 * t + 0] - tau, 0.f),
                                           fmaxf(z[4 * t + 1] - tau, 0.f));
            __half2 h1 = __floats2half2_rn(fmaxf(z[4 * t + 2] - tau, 0.f),
                                           fmaxf(z[4 * t + 3] - tau, 0.f));
            uint2 pk;
            pk.x = *reinterpret_cast<unsigned*>(&h0);
            pk.y = *reinterpret_cast<unsigned*>(&h1);
            *reinterpret_cast<uint2*>(dst + (t << 7) + base) = pk;
        } else if (t == full) {
            float p0 = ((t << 7) + base + 0 < n) ? fmaxf(z[4 * t + 0] - tau, 0.f) : 0.f;
            float p1 = ((t << 7) + base + 1 < n) ? fmaxf(z[4 * t + 1] - tau, 0.f) : 0.f;
            float p2 = ((t << 7) + base + 2 < n) ? fmaxf(z[4 * t + 2] - tau, 0.f) : 0.f;
            float p3 = ((t << 7) + base + 3 < n) ? fmaxf(z[4 * t + 3] - tau, 0.f) : 0.f;
            __half2 h0 = __floats2half2_rn(p0, p1);
            __half2 h1 = __floats2half2_rn(p2, p3);
            uint2 pk;
            pk.x = *reinterpret_cast<unsigned*>(&h0);
            pk.y = *reinterpret_cast<unsigned*>(&h1);
            *reinterpret_cast<uint2*>(dst + (t << 7) + base) = pk;
        } else if (t < EC) {
            *reinterpret_cast<uint2*>(dst + (t << 7) + base) = make_uint2(0u, 0u);
        }
    }
    // lead pad (4 halves) + trail pad (4 halves, only if consumers reach it)
    if (lane == 0) {
        *reinterpret_cast<uint2*>(dst - 4) = make_uint2(0u, 0u);
        if (E > 2048) *reinterpret_cast<uint2*>(dst + 2048) = make_uint2(0u, 0u);
    }
    // zero guard rows (full padded width: 2056 halves = 257 uint4)
    if (i == 0) {
        uint4* gr = reinterpret_cast<uint4*>(g_probs + (size_t)c * ROWS_P * LS);
        const uint4 z4 = make_uint4(0u, 0u, 0u, 0u);
        for (int j = lane; j < LS / 8; j += 32) gr[j] = z4;
    }
    if (i == L - 1) {
        uint4* gr = reinterpret_cast<uint4*>(
            g_probs + ((size_t)c * ROWS_P + (size_t)(L + 1)) * LS);
        const uint4 z4 = make_uint4(0u, 0u, 0u, 0u);
        for (int j = lane; j < LS / 8; j += 32) gr[j] = z4;
    }
}

// ---------------------------------------------------------------------------
// Kernel 2: grouped 3x3 conv + bias + causal zero, TWO output rows per block.
// Stages 4 input rows (16 planes) fp16->fp32 into smem; inner loop fp32 FMA.
// grid = (4 tiles of 512, L/2 row-pairs, 4 groups), 128 threads.
// ---------------------------------------------------------------------------
__global__ void __launch_bounds__(128) conv3x3_group(const float* __restrict__ weight,
                                                     const float* __restrict__ bias,
                                                     float* __restrict__ out) {
    const int g   = blockIdx.z;
    const int i0  = blockIdx.y * 2;
    const int j0  = blockIdx.x * 512;
    const int tid = threadIdx.x;

    if (j0 > i0 + 1) {  // both rows entirely above diagonal -> zeros
        const float4 z4 = make_float4(0.f, 0.f, 0.f, 0.f);
#pragma unroll
        for (int ro = 0; ro < 2; ro++)
#pragma unroll
            for (int co = 0; co < 4; co++) {
                size_t o = ((size_t)(g * 4 + co) * L + (size_t)(i0 + ro)) * L
                         + (size_t)(j0 + tid * 4);
                *reinterpret_cast<float4*>(out + o) = z4;
            }
        return;
    }

    __shared__ float s_in[16][528];   // fp32 planes: 520 used, stride-pad 528
    __shared__ float s_w[144];
    __shared__ float s_b[4];

    for (int e = tid; e < 144; e += 128) s_w[e] = weight[g * 144 + e];
    if (tid < 4) s_b[tid] = bias[g * 4 + tid];

    // staging: LDG.64 of 4 halves -> convert -> STS.128 float4. 130 per plane.
#pragma unroll
    for (int u = 0; u < 4; u++) {
#pragma unroll
        for (int r = 0; r < 4; r++) {
            const uint2* src = reinterpret_cast<const uint2*>(
                g_probs + ((size_t)(g * 4 + u) * ROWS_P + (size_t)(i0 + r)) * LS + (size_t)j0);
            float4* dp = reinterpret_cast<float4*>(&s_in[u * 4 + r][0]);
            {
                uint2 v = src[tid];
                float2 f0 = __half22float2(*reinterpret_cast<__half2*>(&v.x));
                float2 f1 = __half22float2(*reinterpret_cast<__half2*>(&v.y));
                dp[tid] = make_float4(f0.x, f0.y, f1.x, f1.y);
            }
            if (tid < 2) {
                uint2 v = src[128 + tid];
                float2 f0 = __half22float2(*reinterpret_cast<__half2*>(&v.x));
                float2 f1 = __half22float2(*reinterpret_cast<__half2*>(&v.y));
                dp[128 + tid] = make_float4(f0.x, f0.y, f1.x, f1.y);
            }
        }
    }
    __syncthreads();

    float acc[2][4][4];
#pragma unroll
    for (int ro = 0; ro < 2; ro++)
#pragma unroll
        for (int co = 0; co < 4; co++)
#pragma unroll
            for (int q = 0; q < 4; q++) acc[ro][co][q] = s_b[co];

#pragma unroll
    for (int u = 0; u < 4; u++) {
        float win[4][6];
#pragma unroll
        for (int r = 0; r < 4; r++) {
            const float4* rowp = reinterpret_cast<const float4*>(&s_in[u * 4 + r][0]);
            const float4 a = rowp[tid];
            const float4 b = rowp[tid + 1];
            const float4 cc = rowp[tid + 2];
            win[r][0] = a.w; win[r][1] = b.x; win[r][2] = b.y;
            win[r][3] = b.z; win[r][4] = b.w; win[r][5] = cc.x;
        }
#pragma unroll
        for (int ro = 0; ro < 2; ro++) {
#pragma unroll
            for (int kh = 0; kh < 3; kh++) {
                const float* v = win[ro + kh];
#pragma unroll
                for (int co = 0; co < 4; co++) {
                    const float w0 = s_w[co * 36 + u * 9 + kh * 3 + 0];
                    const float w1 = s_w[co * 36 + u * 9 + kh * 3 + 1];
                    const float w2 = s_w[co * 36 + u * 9 + kh * 3 + 2];
                    acc[ro][co][0] += v[0] * w0 + v[1] * w1 + v[2] * w2;
                    acc[ro][co][1] += v[1] * w0 + v[2] * w1 + v[3] * w2;
                    acc[ro][co][2] += v[2] * w0 + v[3] * w1 + v[4] * w2;
                    acc[ro][co][3] += v[3] * w0 + v[4] * w1 + v[5] * w2;
                }
            }
        }
    }

    const int colb = j0 + tid * 4;
#pragma unroll
    for (int ro = 0; ro < 2; ro++) {
        const int ii = i0 + ro;
#pragma unroll
        for (int co = 0; co < 4; co++) {
            float4 r4;
            r4.x = (colb + 0 <= ii) ? acc[ro][co][0] : 0.f;
            r4.y = (colb + 1 <= ii) ? acc[ro][co][1] : 0.f;
            r4.z = (colb + 2 <= ii) ? acc[ro][co][2] : 0.f;
            r4.w = (colb + 3 <= ii) ? acc[ro][co][3] : 0.f;
            size_t o = ((size_t)(g * 4 + co) * L + (size_t)ii) * L + (size_t)colb;
            *reinterpret_cast<float4*>(out + o) = r4;
        }
    }
}

extern "C" void kernel_launch(void* const* d_in, const int* in_sizes, int n_in,
                              void* d_out, int out_size) {
    const float* scores = (const float*)d_in[0];
    const float* weight = (const float*)d_in[1];
    const float* bias   = (const float*)d_in[2];
    float* out = (float*)d_out;

    sparsemax_rows<<<dim3(L / 8, CIN), 256>>>(scores);
    conv3x3_group<<<dim3(L / 512, L / 2, GROUPS), 128>>>(weight, bias, out);
}